// round 4
// baseline (speedup 1.0000x reference)
#include <cuda_runtime.h>
#include <cuda_bf16.h>
#include <mma.h>
#include <cstdint>

using namespace nvcuda;

#define N_NODES 100000
#define N_EDGES 1600000
#define N_PAD   100096                 // 782 * 128, padded for unpredicated wmma stores
#define SCAN_B  512
#define NB1     ((N_NODES + SCAN_B - 1) / SCAN_B)   // 196

// ---------------- scratch (static device memory; no allocs) ----------------
__device__ float g_bufA[N_PAD * 128];   // h1 / h2 (pre-aggregation GEMM out)
__device__ float g_bufB[N_PAD * 128];   // out1
__device__ float g_bufC[N_PAD * 128];   // s = out2 + out1
__device__ int   g_deg[N_NODES];
__device__ float g_dinv[N_NODES];
__device__ int   g_off[N_NODES];
__device__ int   g_cur[N_NODES];
__device__ int   g_csr_src[N_EDGES];
__device__ float g_csr_w[N_EDGES];
__device__ int   g_bsum[256];
__device__ __nv_bfloat16 g_w1t_hi[128 * 128];   // [n][k] = col-major B
__device__ __nv_bfloat16 g_w1t_lo[128 * 128];
__device__ __nv_bfloat16 g_w2t_hi[128 * 128];
__device__ __nv_bfloat16 g_w2t_lo[128 * 128];

// ---------------- graph preprocessing ----------------
__global__ void k_init() {
    int i = blockIdx.x * blockDim.x + threadIdx.x;
    if (i < N_NODES) g_deg[i] = 1;   // self-loop
}
__global__ void k_count(const int* __restrict__ ei) {
    int e = blockIdx.x * blockDim.x + threadIdx.x;
    if (e < N_EDGES) atomicAdd(&g_deg[ei[N_EDGES + e]], 1);
}
__global__ void k_scan1() {
    __shared__ int sh[SCAN_B];
    int tid = threadIdx.x;
    int i = blockIdx.x * SCAN_B + tid;
    int v = (i < N_NODES) ? (g_deg[i] - 1) : 0;
    sh[tid] = v;
    __syncthreads();
    for (int ofs = 1; ofs < SCAN_B; ofs <<= 1) {
        int t = (tid >= ofs) ? sh[tid - ofs] : 0;
        __syncthreads();
        sh[tid] += t;
        __syncthreads();
    }
    if (i < N_NODES) g_off[i] = sh[tid] - v;
    if (tid == SCAN_B - 1) g_bsum[blockIdx.x] = sh[tid];
}
__global__ void k_scan2() {
    __shared__ int sh[256];
    int tid = threadIdx.x;
    int v = (tid < NB1) ? g_bsum[tid] : 0;
    sh[tid] = v;
    __syncthreads();
    for (int ofs = 1; ofs < 256; ofs <<= 1) {
        int t = (tid >= ofs) ? sh[tid - ofs] : 0;
        __syncthreads();
        sh[tid] += t;
        __syncthreads();
    }
    g_bsum[tid] = sh[tid] - v;
}
__global__ void k_scan3() {   // also computes dinv (folded k_dinv)
    int i = blockIdx.x * blockDim.x + threadIdx.x;
    if (i < N_NODES) {
        int o = g_off[i] + g_bsum[i / SCAN_B];
        g_off[i] = o;
        g_cur[i] = o;
        g_dinv[i] = rsqrtf((float)g_deg[i]);
    }
}
__global__ void k_scatter(const int* __restrict__ ei) {
    int e = blockIdx.x * blockDim.x + threadIdx.x;
    if (e < N_EDGES) {
        int s = ei[e];
        int d = ei[N_EDGES + e];
        int p = atomicAdd(&g_cur[d], 1);
        g_csr_src[p] = s;
        g_csr_w[p]   = g_dinv[s] * g_dinv[d];
    }
}

// ---------------- W split/transpose: Wt[n][k] = hi/lo of W[k][n] ----------
__global__ void k_wconv(const float* __restrict__ W,
                        __nv_bfloat16* __restrict__ hi,
                        __nv_bfloat16* __restrict__ lo) {
    int idx = blockIdx.x * blockDim.x + threadIdx.x;   // 16384
    if (idx >= 128 * 128) return;
    int n = idx & 127, k = idx >> 7;
    float v = W[k * 128 + n];
    __nv_bfloat16 h = __float2bfloat16(v);
    float r = v - __bfloat162float(h);
    hi[n * 128 + k] = h;
    lo[n * 128 + k] = __float2bfloat16(r);
}

// ---------------- HMMA GEMM: C[N,128] = A[N,128] @ W[128,128] -------------
// 3-term bf16 split: Ahi*Whi + Alo*Whi + Ahi*Wlo, fp32 accumulators.
// Block: 256 threads = 8 warps in a 4(M) x 2(N) warp grid; warp tile 32x64.
// C is written unpredicated into padded scratch (N_PAD rows).
#define LDS_T 136        // 128 + 8 bf16 pad (272 B row stride, 16B aligned)

__global__ __launch_bounds__(256, 1)
void k_hgemm(const float* __restrict__ A,
             const __nv_bfloat16* __restrict__ wt_hi,
             const __nv_bfloat16* __restrict__ wt_lo,
             float* __restrict__ C) {
    extern __shared__ __nv_bfloat16 sm[];
    __nv_bfloat16* Ahi = sm;                  // [128][LDS_T] row-major
    __nv_bfloat16* Alo = Ahi + 128 * LDS_T;
    __nv_bfloat16* Whi = Alo + 128 * LDS_T;   // [n][k] = col-major B, ld LDS_T
    __nv_bfloat16* Wlo = Whi + 128 * LDS_T;

    int tid  = threadIdx.x;
    int wid  = tid >> 5;
    int row0 = blockIdx.x * 128;

    // ---- load A tile (fp32 -> bf16 hi/lo) ----
    {
        int r  = tid >> 1;
        int kh = (tid & 1) << 6;
        int gr = row0 + r;
        const float4* Ag = (const float4*)A;
        #pragma unroll
        for (int j = 0; j < 8; j++) {
            int k0 = kh + j * 8;
            float4 va = make_float4(0.f, 0.f, 0.f, 0.f);
            float4 vb = make_float4(0.f, 0.f, 0.f, 0.f);
            if (gr < N_NODES) {
                va = Ag[gr * 32 + (k0 >> 2)];
                vb = Ag[gr * 32 + (k0 >> 2) + 1];
            }
            float f[8] = {va.x, va.y, va.z, va.w, vb.x, vb.y, vb.z, vb.w};
            __nv_bfloat162 hp[4], lp[4];
            #pragma unroll
            for (int t = 0; t < 4; t++) {
                __nv_bfloat16 h0 = __float2bfloat16(f[2 * t]);
                __nv_bfloat16 h1 = __float2bfloat16(f[2 * t + 1]);
                float l0 = f[2 * t]     - __bfloat162float(h0);
                float l1 = f[2 * t + 1] - __bfloat162float(h1);
                hp[t] = __nv_bfloat162(h0, h1);
                lp[t] = __floats2bfloat162_rn(l0, l1);
            }
            *(uint4*)&Ahi[r * LDS_T + k0] = *(uint4*)hp;
            *(uint4*)&Alo[r * LDS_T + k0] = *(uint4*)lp;
        }
    }
    // ---- load W tiles (pre-split bf16, [n][k]) ----
    {
        int n  = tid >> 1;
        int kh = (tid & 1) << 6;
        #pragma unroll
        for (int j = 0; j < 8; j++) {
            int k0 = kh + j * 8;
            *(uint4*)&Whi[n * LDS_T + k0] = *(const uint4*)&wt_hi[n * 128 + k0];
            *(uint4*)&Wlo[n * LDS_T + k0] = *(const uint4*)&wt_lo[n * 128 + k0];
        }
    }
    __syncthreads();

    int wm = wid & 3;    // 4 M-tiles of 32 rows
    int wn = wid >> 2;   // 2 N-tiles of 64 cols

    wmma::fragment<wmma::accumulator, 16, 16, 16, float> acc[2][4];
    #pragma unroll
    for (int i = 0; i < 2; i++)
        #pragma unroll
        for (int j = 0; j < 4; j++) wmma::fill_fragment(acc[i][j], 0.0f);

    for (int ks = 0; ks < 8; ks++) {
        int k0 = ks * 16;
        wmma::fragment<wmma::matrix_a, 16, 16, 16, __nv_bfloat16, wmma::row_major> ah[2], al[2];
        #pragma unroll
        for (int i = 0; i < 2; i++) {
            int r = wm * 32 + i * 16;
            wmma::load_matrix_sync(ah[i], &Ahi[r * LDS_T + k0], LDS_T);
            wmma::load_matrix_sync(al[i], &Alo[r * LDS_T + k0], LDS_T);
        }
        #pragma unroll
        for (int j = 0; j < 4; j++) {
            int n0 = wn * 64 + j * 16;
            wmma::fragment<wmma::matrix_b, 16, 16, 16, __nv_bfloat16, wmma::col_major> bh, bl;
            wmma::load_matrix_sync(bh, &Whi[n0 * LDS_T + k0], LDS_T);
            wmma::load_matrix_sync(bl, &Wlo[n0 * LDS_T + k0], LDS_T);
            #pragma unroll
            for (int i = 0; i < 2; i++) {
                wmma::mma_sync(acc[i][j], ah[i], bh, acc[i][j]);
                wmma::mma_sync(acc[i][j], al[i], bh, acc[i][j]);
                wmma::mma_sync(acc[i][j], ah[i], bl, acc[i][j]);
            }
        }
    }

    // ---- store (C padded to N_PAD rows: no bounds checks needed) ----
    #pragma unroll
    for (int i = 0; i < 2; i++) {
        int r = row0 + wm * 32 + i * 16;
        #pragma unroll
        for (int j = 0; j < 4; j++) {
            int n0 = wn * 64 + j * 16;
            wmma::store_matrix_sync(&C[r * 128 + n0], acc[i][j], 128, wmma::mem_row_major);
        }
    }
}

// ---------------- aggregation: one warp per node, float4 per lane ----------
__global__ __launch_bounds__(256)
void k_agg(const float* __restrict__ h, const float* __restrict__ bias,
           const float* __restrict__ prev, float* __restrict__ out,
           int addprev) {
    int warp = threadIdx.x >> 5;
    int lane = threadIdx.x & 31;
    int i = blockIdx.x * 8 + warp;
    if (i >= N_NODES) return;

    const float4* h4 = (const float4*)h;
    float di = g_dinv[i];
    float sl = di * di;
    float4 acc = h4[i * 32 + lane];
    acc.x *= sl; acc.y *= sl; acc.z *= sl; acc.w *= sl;

    int cnt  = g_deg[i] - 1;
    int base = g_off[i];
    int e = 0;
    for (; e + 8 <= cnt; e += 8) {
        int s[8]; float w[8];
        #pragma unroll
        for (int j = 0; j < 8; j++) {
            s[j] = g_csr_src[base + e + j];
            w[j] = g_csr_w[base + e + j];
        }
        float4 v[8];
        #pragma unroll
        for (int j = 0; j < 8; j++) v[j] = h4[s[j] * 32 + lane];
        #pragma unroll
        for (int j = 0; j < 8; j++) {
            acc.x += w[j] * v[j].x; acc.y += w[j] * v[j].y;
            acc.z += w[j] * v[j].z; acc.w += w[j] * v[j].w;
        }
    }
    for (; e < cnt; e++) {
        int   sj = g_csr_src[base + e];
        float wj = g_csr_w[base + e];
        float4 v = h4[sj * 32 + lane];
        acc.x += wj * v.x; acc.y += wj * v.y;
        acc.z += wj * v.z; acc.w += wj * v.w;
    }

    float4 bv = ((const float4*)bias)[lane];
    acc.x = fmaxf(acc.x + bv.x, 0.f);
    acc.y = fmaxf(acc.y + bv.y, 0.f);
    acc.z = fmaxf(acc.z + bv.z, 0.f);
    acc.w = fmaxf(acc.w + bv.w, 0.f);

    if (addprev) {
        float4 p = ((const float4*)prev)[i * 32 + lane];
        acc.x += p.x; acc.y += p.y; acc.z += p.z; acc.w += p.w;
    }
    ((float4*)out)[i * 32 + lane] = acc;
}

// ---------------- classifier GEMM: C[N,40] = S[N,128] @ Wc[128,40] + bc ----
__global__ __launch_bounds__(256, 1)
void k_gemm40(const float* __restrict__ A, const float* __restrict__ W,
              const float* __restrict__ bias, float* __restrict__ C) {
    extern __shared__ float smf[];
    float* As = smf;               // [k][m] 128x128
    float* Ws = smf + 128 * 128;   // [k][40]
    int tid  = threadIdx.x;
    int row0 = blockIdx.x * 128;

    for (int idx = tid; idx < 128 * 40; idx += 256) Ws[idx] = W[idx];
    {
        int r  = tid >> 1;
        int kh = (tid & 1) * 64;
        int gr = row0 + r;
        const float4* Ag = (const float4*)A;
        #pragma unroll
        for (int j = 0; j < 16; j++) {
            int k = kh + j * 4;
            float4 v = make_float4(0.f, 0.f, 0.f, 0.f);
            if (gr < N_NODES) v = Ag[gr * 32 + (k >> 2)];
            As[(k + 0) * 128 + r] = v.x;
            As[(k + 1) * 128 + r] = v.y;
            As[(k + 2) * 128 + r] = v.z;
            As[(k + 3) * 128 + r] = v.w;
        }
    }
    __syncthreads();

    int rg = tid >> 3;
    int c0 = (tid & 7) * 5;
    float acc[4][5];
    #pragma unroll
    for (int i = 0; i < 4; i++)
        #pragma unroll
        for (int j = 0; j < 5; j++) acc[i][j] = 0.f;

    #pragma unroll 4
    for (int k = 0; k < 128; k++) {
        float4 a = *(const float4*)&As[k * 128 + rg * 4];
        float av[4] = {a.x, a.y, a.z, a.w};
        float bv[5];
        #pragma unroll
        for (int j = 0; j < 5; j++) bv[j] = Ws[k * 40 + c0 + j];
        #pragma unroll
        for (int i = 0; i < 4; i++)
            #pragma unroll
            for (int j = 0; j < 5; j++) acc[i][j] += av[i] * bv[j];
    }

    float bcv[5];
    #pragma unroll
    for (int j = 0; j < 5; j++) bcv[j] = bias[c0 + j];
    #pragma unroll
    for (int i = 0; i < 4; i++) {
        int row = row0 + rg * 4 + i;
        if (row < N_NODES) {
            #pragma unroll
            for (int j = 0; j < 5; j++)
                C[row * 40 + c0 + j] = acc[i][j] + bcv[j];
        }
    }
}

// ---------------- launch ----------------
extern "C" void kernel_launch(void* const* d_in, const int* in_sizes, int n_in,
                              void* d_out, int out_size) {
    const float* x  = (const float*)d_in[0];
    const float* W1 = (const float*)d_in[1];
    const float* b1 = (const float*)d_in[2];
    const float* W2 = (const float*)d_in[3];
    const float* b2 = (const float*)d_in[4];
    const float* Wc = (const float*)d_in[5];
    const float* bc = (const float*)d_in[6];
    const int*   ei = (const int*)d_in[7];
    float* out = (float*)d_out;

    const int SMEM_HG  = 4 * 128 * LDS_T * 2;                 // 139264 B
    const int SMEM_G40 = 128 * 128 * 4 + 128 * 40 * 4;        // 86 KB
    cudaFuncSetAttribute(k_hgemm,  cudaFuncAttributeMaxDynamicSharedMemorySize, SMEM_HG);
    cudaFuncSetAttribute(k_gemm40, cudaFuncAttributeMaxDynamicSharedMemorySize, SMEM_G40);

    float *pA, *pB, *pC;
    cudaGetSymbolAddress((void**)&pA, g_bufA);
    cudaGetSymbolAddress((void**)&pB, g_bufB);
    cudaGetSymbolAddress((void**)&pC, g_bufC);
    __nv_bfloat16 *w1h, *w1l, *w2h, *w2l;
    cudaGetSymbolAddress((void**)&w1h, g_w1t_hi);
    cudaGetSymbolAddress((void**)&w1l, g_w1t_lo);
    cudaGetSymbolAddress((void**)&w2h, g_w2t_hi);
    cudaGetSymbolAddress((void**)&w2l, g_w2t_lo);

    const int GN  = (N_NODES + 255) / 256;   // 391
    const int GE  = (N_EDGES + 255) / 256;   // 6250
    const int GT  = (N_NODES + 127) / 128;   // 782
    const int GAG = (N_NODES + 7) / 8;       // 12500

    // graph preprocessing
    k_init<<<GN, 256>>>();
    k_count<<<GE, 256>>>(ei);
    k_scan1<<<NB1, SCAN_B>>>();
    k_scan2<<<1, 256>>>();
    k_scan3<<<GN, 256>>>();
    k_scatter<<<GE, 256>>>(ei);

    // weight split/transpose
    k_wconv<<<64, 256>>>(W1, w1h, w1l);
    k_wconv<<<64, 256>>>(W2, w2h, w2l);

    // layer 1
    k_hgemm<<<GT, 256, SMEM_HG>>>(x, w1h, w1l, pA);
    k_agg<<<GAG, 256>>>(pA, b1, nullptr, pB, 0);
    // layer 2
    k_hgemm<<<GT, 256, SMEM_HG>>>(pB, w2h, w2l, pA);
    k_agg<<<GAG, 256>>>(pA, b2, pB, pC, 1);
    // classifier
    k_gemm40<<<GT, 256, SMEM_G40>>>(pC, Wc, bc, out);
}

// round 6
// speedup vs baseline: 1.3252x; 1.3252x over previous
#include <cuda_runtime.h>
#include <cuda_bf16.h>
#include <cstdint>

#define N_NODES 100000
#define N_EDGES 1600000
#define N_PAD   100096
#define NB_OFF  ((N_NODES + 511) / 512)   // 196

// ---------------- scratch (static device memory; no allocs) ----------------
__device__ float g_bufA[N_PAD * 128];   // h1 / h2 (pre-aggregation GEMM out)
__device__ float g_bufB[N_PAD * 128];   // out1
__device__ float g_bufC[N_PAD * 128];   // s = out2 + out1
__device__ int   g_deg[N_NODES];        // real in-edge count (no self-loop)
__device__ int   g_off[N_NODES];
__device__ int   g_cur[N_NODES];
__device__ int   g_csr_src[N_EDGES];
__device__ float g_csr_w[N_EDGES];
__device__ int   g_total[1];

// ---------------- f32x2 packed-FMA helpers (PTX-only on Blackwell) ---------
__device__ __forceinline__ unsigned long long pack2(float a, float b) {
    unsigned long long r;
    asm("mov.b64 %0, {%1, %2};" : "=l"(r) : "f"(a), "f"(b));
    return r;
}
__device__ __forceinline__ void unpack2(float& a, float& b, unsigned long long v) {
    asm("mov.b64 {%0, %1}, %2;" : "=f"(a), "=f"(b) : "l"(v));
}
__device__ __forceinline__ void fma2(unsigned long long& d, unsigned long long a,
                                     unsigned long long b, unsigned long long c) {
    asm("fma.rn.f32x2 %0, %1, %2, %3;" : "=l"(d) : "l"(a), "l"(b), "l"(c));
}

// ---------------- graph preprocessing (3 kernels) ----------------
__global__ void k_count(const int* __restrict__ ei) {
    int e = blockIdx.x * blockDim.x + threadIdx.x;
    if (e < N_EDGES) atomicAdd(&g_deg[ei[N_EDGES + e]], 1);
}

// one-pass offsets: block shuffle-scan + atomic block base (order-free CSR)
__global__ __launch_bounds__(512)
void k_offsets() {
    __shared__ int wsum[16];
    __shared__ int base;
    int tid  = threadIdx.x;
    int lane = tid & 31;
    int w    = tid >> 5;
    int i = blockIdx.x * 512 + tid;
    int v = (i < N_NODES) ? g_deg[i] : 0;

    int inc = v;
    #pragma unroll
    for (int o = 1; o < 32; o <<= 1) {
        int t = __shfl_up_sync(0xFFFFFFFFu, inc, o);
        if (lane >= o) inc += t;
    }
    if (lane == 31) wsum[w] = inc;
    __syncthreads();
    if (w == 0) {
        int s = (lane < 16) ? wsum[lane] : 0;
        #pragma unroll
        for (int o = 1; o < 16; o <<= 1) {
            int t = __shfl_up_sync(0xFFFFFFFFu, s, o);
            if (lane >= o) s += t;
        }
        if (lane < 16) wsum[lane] = s;
    }
    __syncthreads();
    if (tid == 0) base = atomicAdd(&g_total[0], wsum[15]);
    int excl = inc - v + (w > 0 ? wsum[w - 1] : 0);
    __syncthreads();
    if (i < N_NODES) {
        int o = base + excl;
        g_off[i] = o;
        g_cur[i] = o;
    }
}

__global__ void k_scatter(const int* __restrict__ ei) {
    int e = blockIdx.x * blockDim.x + threadIdx.x;
    if (e < N_EDGES) {
        int s = ei[e];
        int d = ei[N_EDGES + e];
        int p = atomicAdd(&g_cur[d], 1);
        float ws = rsqrtf((float)(g_deg[s] + 1));
        float wd = rsqrtf((float)(g_deg[d] + 1));
        g_csr_src[p] = s;
        g_csr_w[p]   = ws * wd;
    }
}

// ---------------- GEMM: C[N,128] = A[N,128] @ W[128,128] (f32x2 packed) ----
__global__ __launch_bounds__(256, 1)
void k_gemm128(const float* __restrict__ A, const float* __restrict__ W,
               float* __restrict__ C) {
    extern __shared__ float sm[];
    float* As = sm;              // [k][m]  (transposed A tile), 128x128
    float* Ws = sm + 128 * 128;  // [k][n], 128x128
    int tid  = threadIdx.x;
    int row0 = blockIdx.x * 128;

    {
        const float4* Wg  = (const float4*)W;
        float4*       Wsh = (float4*)Ws;
        #pragma unroll
        for (int i = 0; i < 16; i++) Wsh[tid + 256 * i] = Wg[tid + 256 * i];
    }
    {
        int r  = tid >> 1;
        int kh = (tid & 1) * 64;
        int gr = row0 + r;
        const float4* Ag = (const float4*)A;
        #pragma unroll
        for (int j = 0; j < 16; j++) {
            int k = kh + j * 4;
            float4 v = make_float4(0.f, 0.f, 0.f, 0.f);
            if (gr < N_NODES) v = Ag[gr * 32 + (k >> 2)];
            As[(k + 0) * 128 + r] = v.x;
            As[(k + 1) * 128 + r] = v.y;
            As[(k + 2) * 128 + r] = v.z;
            As[(k + 3) * 128 + r] = v.w;
        }
    }
    __syncthreads();

    int tx = tid & 15, ty = tid >> 4;    // 8x8 micro-tile per thread
    unsigned long long acc[8][4];
    #pragma unroll
    for (int i = 0; i < 8; i++)
        #pragma unroll
        for (int j = 0; j < 4; j++) acc[i][j] = 0ull;

    #pragma unroll 8
    for (int k = 0; k < 128; k++) {
        float4 a0 = *(const float4*)&As[k * 128 + ty * 8];
        float4 a1 = *(const float4*)&As[k * 128 + ty * 8 + 4];
        const unsigned long long* Bp =
            (const unsigned long long*)&Ws[k * 128 + tx * 8];
        unsigned long long bb0 = Bp[0], bb1 = Bp[1], bb2 = Bp[2], bb3 = Bp[3];
        float av[8] = {a0.x, a0.y, a0.z, a0.w, a1.x, a1.y, a1.z, a1.w};
        #pragma unroll
        for (int i = 0; i < 8; i++) {
            unsigned long long aa = pack2(av[i], av[i]);
            fma2(acc[i][0], aa, bb0, acc[i][0]);
            fma2(acc[i][1], aa, bb1, acc[i][1]);
            fma2(acc[i][2], aa, bb2, acc[i][2]);
            fma2(acc[i][3], aa, bb3, acc[i][3]);
        }
    }

    float4* Cg = (float4*)C;
    #pragma unroll
    for (int i = 0; i < 8; i++) {
        int row = row0 + ty * 8 + i;
        if (row < N_NODES) {
            float4 lo, hi;
            unpack2(lo.x, lo.y, acc[i][0]);
            unpack2(lo.z, lo.w, acc[i][1]);
            unpack2(hi.x, hi.y, acc[i][2]);
            unpack2(hi.z, hi.w, acc[i][3]);
            Cg[row * 32 + tx * 2]     = lo;
            Cg[row * 32 + tx * 2 + 1] = hi;
        }
    }
}

// ---------------- aggregation: one warp per node, float4 per lane ----------
__global__ __launch_bounds__(256)
void k_agg(const float* __restrict__ h, const float* __restrict__ bias,
           const float* __restrict__ prev, float* __restrict__ out,
           int addprev) {
    int warp = threadIdx.x >> 5;
    int lane = threadIdx.x & 31;
    int i = blockIdx.x * 8 + warp;
    if (i >= N_NODES) return;

    const float4* h4 = (const float4*)h;
    int   cnt = g_deg[i];
    float di  = rsqrtf((float)(cnt + 1));
    float sl  = di * di;                      // self-loop weight
    float4 acc = h4[i * 32 + lane];
    acc.x *= sl; acc.y *= sl; acc.z *= sl; acc.w *= sl;

    int base = g_off[i];
    int e = 0;
    for (; e + 8 <= cnt; e += 8) {
        int s[8]; float w[8];
        #pragma unroll
        for (int j = 0; j < 8; j++) {
            s[j] = g_csr_src[base + e + j];
            w[j] = g_csr_w[base + e + j];
        }
        float4 v[8];
        #pragma unroll
        for (int j = 0; j < 8; j++) v[j] = h4[s[j] * 32 + lane];
        #pragma unroll
        for (int j = 0; j < 8; j++) {
            acc.x += w[j] * v[j].x; acc.y += w[j] * v[j].y;
            acc.z += w[j] * v[j].z; acc.w += w[j] * v[j].w;
        }
    }
    for (; e < cnt; e++) {
        int   sj = g_csr_src[base + e];
        float wj = g_csr_w[base + e];
        float4 v = h4[sj * 32 + lane];
        acc.x += wj * v.x; acc.y += wj * v.y;
        acc.z += wj * v.z; acc.w += wj * v.w;
    }

    float4 bv = ((const float4*)bias)[lane];
    acc.x = fmaxf(acc.x + bv.x, 0.f);
    acc.y = fmaxf(acc.y + bv.y, 0.f);
    acc.z = fmaxf(acc.z + bv.z, 0.f);
    acc.w = fmaxf(acc.w + bv.w, 0.f);

    if (addprev) {
        float4 p = ((const float4*)prev)[i * 32 + lane];
        acc.x += p.x; acc.y += p.y; acc.z += p.z; acc.w += p.w;
    }
    ((float4*)out)[i * 32 + lane] = acc;
}

// ---------------- classifier GEMM: C[N,40] = S[N,128] @ Wc[128,40] + bc ----
__global__ __launch_bounds__(256, 1)
void k_gemm40(const float* __restrict__ A, const float* __restrict__ W,
              const float* __restrict__ bias, float* __restrict__ C) {
    extern __shared__ float smf[];
    float* As = smf;               // [k][m] 128x128
    float* Ws = smf + 128 * 128;   // [k][40]
    int tid  = threadIdx.x;
    int row0 = blockIdx.x * 128;

    for (int idx = tid; idx < 128 * 40; idx += 256) Ws[idx] = W[idx];
    {
        int r  = tid >> 1;
        int kh = (tid & 1) * 64;
        int gr = row0 + r;
        const float4* Ag = (const float4*)A;
        #pragma unroll
        for (int j = 0; j < 16; j++) {
            int k = kh + j * 4;
            float4 v = make_float4(0.f, 0.f, 0.f, 0.f);
            if (gr < N_NODES) v = Ag[gr * 32 + (k >> 2)];
            As[(k + 0) * 128 + r] = v.x;
            As[(k + 1) * 128 + r] = v.y;
            As[(k + 2) * 128 + r] = v.z;
            As[(k + 3) * 128 + r] = v.w;
        }
    }
    __syncthreads();

    int rg = tid >> 3;          // 32 row groups of 4 rows
    int c0 = (tid & 7) * 5;     // 8 col groups of 5 cols
    unsigned long long acc2[2][5];   // row-pairs (0,1),(2,3) x 5 cols
    #pragma unroll
    for (int i = 0; i < 2; i++)
        #pragma unroll
        for (int j = 0; j < 5; j++) acc2[i][j] = 0ull;

    #pragma unroll 4
    for (int k = 0; k < 128; k++) {
        float4 a = *(const float4*)&As[k * 128 + rg * 4];
        unsigned long long a01 = pack2(a.x, a.y);
        unsigned long long a23 = pack2(a.z, a.w);
        #pragma unroll
        for (int j = 0; j < 5; j++) {
            float b = Ws[k * 40 + c0 + j];
            unsigned long long bb = pack2(b, b);
            fma2(acc2[0][j], a01, bb, acc2[0][j]);
            fma2(acc2[1][j], a23, bb, acc2[1][j]);
        }
    }

    float bcv[5];
    #pragma unroll
    for (int j = 0; j < 5; j++) bcv[j] = bias[c0 + j];
    #pragma unroll
    for (int i = 0; i < 2; i++) {
        float r0[5], r1[5];
        #pragma unroll
        for (int j = 0; j < 5; j++) unpack2(r0[j], r1[j], acc2[i][j]);
        int rowa = row0 + rg * 4 + 2 * i;
        int rowb = rowa + 1;
        if (rowa < N_NODES) {
            #pragma unroll
            for (int j = 0; j < 5; j++) C[rowa * 40 + c0 + j] = r0[j] + bcv[j];
        }
        if (rowb < N_NODES) {
            #pragma unroll
            for (int j = 0; j < 5; j++) C[rowb * 40 + c0 + j] = r1[j] + bcv[j];
        }
    }
}

// ---------------- launch ----------------
extern "C" void kernel_launch(void* const* d_in, const int* in_sizes, int n_in,
                              void* d_out, int out_size) {
    const float* x  = (const float*)d_in[0];
    const float* W1 = (const float*)d_in[1];
    const float* b1 = (const float*)d_in[2];
    const float* W2 = (const float*)d_in[3];
    const float* b2 = (const float*)d_in[4];
    const float* Wc = (const float*)d_in[5];
    const float* bc = (const float*)d_in[6];
    const int*   ei = (const int*)d_in[7];
    float* out = (float*)d_out;

    const int SMEM_G128 = 2 * 128 * 128 * 4;                  // 128 KB
    const int SMEM_G40  = 128 * 128 * 4 + 128 * 40 * 4;       // 84.5 KB
    cudaFuncSetAttribute(k_gemm128, cudaFuncAttributeMaxDynamicSharedMemorySize, SMEM_G128);
    cudaFuncSetAttribute(k_gemm40,  cudaFuncAttributeMaxDynamicSharedMemorySize, SMEM_G40);

    float *pA, *pB, *pC;
    cudaGetSymbolAddress((void**)&pA, g_bufA);
    cudaGetSymbolAddress((void**)&pB, g_bufB);
    cudaGetSymbolAddress((void**)&pC, g_bufC);
    int *pDeg, *pTot;
    cudaGetSymbolAddress((void**)&pDeg, g_deg);
    cudaGetSymbolAddress((void**)&pTot, g_total);

    const int GE  = (N_EDGES + 255) / 256;   // 6250
    const int GT  = (N_NODES + 127) / 128;   // 782
    const int GAG = (N_NODES + 7) / 8;       // 12500

    // zero degree counters + offset ticket (graph-capturable async memsets)
    cudaMemsetAsync(pDeg, 0, N_NODES * sizeof(int));
    cudaMemsetAsync(pTot, 0, sizeof(int));

    // preprocessing: 3 kernels
    k_count<<<GE, 256>>>(ei);
    k_offsets<<<NB_OFF, 512>>>();
    k_scatter<<<GE, 256>>>(ei);

    // layer 1
    k_gemm128<<<GT, 256, SMEM_G128>>>(x, W1, pA);
    k_agg<<<GAG, 256>>>(pA, b1, nullptr, pB, 0);
    // layer 2
    k_gemm128<<<GT, 256, SMEM_G128>>>(pB, W2, pA);
    k_agg<<<GAG, 256>>>(pA, b2, pB, pC, 1);
    // classifier
    k_gemm40<<<GT, 256, SMEM_G40>>>(pC, Wc, bc, out);
}